// round 3
// baseline (speedup 1.0000x reference)
#include <cuda_runtime.h>
#include <cuda_bf16.h>

// ---------------------------------------------------------------------------
// Encoder: B=2048 rows of (16 x 512) fp32 state, 2 layers of
//   [LN -> patchify -> qkv dwconv(s2)+BN+pw -> attention(32x32) -> c1d -> lin -> +res]
//   [LN -> patchify -> f1(32->128)+ReLU -> dw3x3+BN+pw(128->128)+ReLU -> f2(128->32) -> +res]
// One CTA per batch row; everything fused in shared memory.
// ---------------------------------------------------------------------------

#define NB      2048
#define LAYERS  2
#define DM      512
#define EPSLN   1e-5f
#define NT      256

// ---- shared memory layout (float offsets) ----
// persistent:
//   SX    [0, 8192)                  : x state 16x512
// attention phase (scratch base 8192):
//   SXP   8192  (32*256 = 8192)      : patches of LN1(x)
//   STMP  16384 (32*64  = 2048)      : dwconv+BN output (per qkv i)
//   SQ    18432 (32*65  = 2080)
//   SK    20512 (32*65)
//   SV    22592 (32*65)
//   SO    24672 (32*65)              : attention output
//   SO16  26752 (16*257 = 4112)      : after c1d          -> end 30864
//   WT    8192  (512*33 = 16896)     : lin_w tile (overlays SXP..SO, all dead) -> end 25088
// ffn phase:
//   ST1   8192 as bf16, 128 rows * 260 cols  = 16640 floats -> end 24832
//   SXP2  24832 (32*256 = 8192)      -> end 33024  (dead after f1)
//   SW1   33024 (128*32 = 4096)      -> end 37120  (dead after f1)
//   SFPW  24832 (128*128 = 16384)    -> end 41216  (loaded after f1)
//   ST2   41216 (128*34 = 4352)      -> end 45568
//   ST3   45568 (128*33 = 4224)      -> end 49792
//   SF2   49792 (32*128 = 4096)      -> end 53888
//   SFDW  53888 (128*12 = 1536)      -> end 55424
#define OFF_SX    0
#define OFF_SXP   8192
#define OFF_STMP  16384
#define OFF_SQ    18432
#define OFF_SK    20512
#define OFF_SV    22592
#define OFF_SO    24672
#define OFF_SO16  26752
#define OFF_WT    8192
#define OFF_ST1   8192
#define OFF_SXP2  24832
#define OFF_SW1   33024
#define OFF_SFPW  24832
#define OFF_ST2   41216
#define OFF_ST3   45568
#define OFF_SF2   49792
#define OFF_SFDW  53888
#define SMEM_FLOATS 55424
#define SMEM_BYTES  (SMEM_FLOATS * 4)

struct Params {
    const float *x;
    const float *ln1_g, *ln1_b, *ln2_g, *ln2_b;
    const float *qkv_dw, *qkv_bng, *qkv_bnb, *qkv_bnm, *qkv_bnv, *qkv_pw;
    const float *position, *c1d_w, *c1d_b, *lin_w, *lin_b;
    const float *f1_w, *f1_b, *fdw_w, *fdw_b;
    const float *f_bng, *f_bnb, *f_bnm, *f_bnv;
    const float *fpw_w, *fpw_b, *f2_w, *f2_b;
    float *out;
};

__device__ __forceinline__ float warp_sum(float v) {
#pragma unroll
    for (int o = 16; o; o >>= 1) v += __shfl_xor_sync(0xffffffffu, v, o);
    return v;
}
__device__ __forceinline__ float warp_max(float v) {
#pragma unroll
    for (int o = 16; o; o >>= 1) v = fmaxf(v, __shfl_xor_sync(0xffffffffu, v, o));
    return v;
}

// LayerNorm over the 512-feature rows of sx, scattered into patch layout:
// dst[d*256 + h*16 + p2] = LN(sx[h][d*16+p2]) * g[j] + b[j],  j = d*16+p2
__device__ __forceinline__ void ln_to_patches(const float* sx, float* dst,
                                              const float* g, const float* bb,
                                              int lane, int wid) {
#pragma unroll
    for (int r = 0; r < 2; r++) {
        int h = wid + 8 * r;
        float s = 0.f, ss = 0.f;
#pragma unroll
        for (int i = 0; i < 16; i++) {
            float v = sx[h * 512 + lane + 32 * i];
            s += v; ss += v * v;
        }
        s = warp_sum(s); ss = warp_sum(ss);
        float mean = s * (1.f / 512.f);
        float var = ss * (1.f / 512.f) - mean * mean;
        float rs = rsqrtf(var + EPSLN);
#pragma unroll
        for (int i = 0; i < 16; i++) {
            int j = lane + 32 * i;
            float v = (sx[h * 512 + j] - mean) * rs * g[j] + bb[j];
            dst[(j >> 4) * 256 + h * 16 + (j & 15)] = v;
        }
    }
}

extern __shared__ float sm[];

__global__ void __launch_bounds__(NT, 1) encoder_kernel(Params p) {
    const int b = blockIdx.x;
    const int tid = threadIdx.x;
    const int lane = tid & 31;
    const int wid = tid >> 5;

    float* sx = sm + OFF_SX;

    // ---- load x (16x512) ----
    {
        const float4* xg = (const float4*)(p.x + (size_t)b * 8192);
        float4* sx4 = (float4*)sx;
#pragma unroll
        for (int it = 0; it < 8; it++) sx4[tid + NT * it] = xg[tid + NT * it];
    }
    __syncthreads();

    for (int l = 0; l < LAYERS; l++) {
        // ================= attention sublayer =================
        ln_to_patches(sx, sm + OFF_SXP, p.ln1_g + l * DM, p.ln1_b + l * DM, lane, wid);
        __syncthreads();

        // ---- q/k/v: depthwise 3x3 s2 + BN + 1x1 pointwise ----
        for (int i = 0; i < 3; i++) {
            const float* sxp = sm + OFF_SXP;
            float* stmp = sm + OFF_STMP;
            const float* dw  = p.qkv_dw  + (size_t)((l * 3 + i) * 32) * 9;
            const float* bng = p.qkv_bng + (l * 3 + i) * 32;
            const float* bnb = p.qkv_bnb + (l * 3 + i) * 32;
            const float* bnm = p.qkv_bnm + (l * 3 + i) * 32;
            const float* bnv = p.qkv_bnv + (l * 3 + i) * 32;
#pragma unroll 2
            for (int it = 0; it < 8; it++) {
                int u = tid + NT * it;
                int c = u >> 6, pos = u & 63;
                int oh = pos >> 3, ow = pos & 7;
                int ch2 = 2 * oh, cw2 = 2 * ow;
                const float* wp = dw + c * 9;
                float acc = 0.f;
#pragma unroll
                for (int kh = 0; kh < 3; kh++) {
                    int ih = ch2 - 1 + kh;
                    if ((unsigned)ih < 16u) {
#pragma unroll
                        for (int kw = 0; kw < 3; kw++) {
                            int iw = cw2 - 1 + kw;
                            if ((unsigned)iw < 16u)
                                acc += sxp[c * 256 + ih * 16 + iw] * wp[kh * 3 + kw];
                        }
                    }
                }
                float sc = bng[c] * rsqrtf(bnv[c] + EPSLN);
                float sh = bnb[c] - bnm[c] * sc;
                stmp[c * 64 + pos] = acc * sc + sh;
            }
            __syncthreads();
            // pointwise 32->32
            const float* pw = p.qkv_pw + (size_t)((l * 3 + i) * 32) * 32;
            float* dstq = sm + OFF_SQ + i * 2080;
#pragma unroll 2
            for (int it = 0; it < 8; it++) {
                int u = tid + NT * it;
                int d = u >> 6, pos = u & 63;
                const float* w = pw + d * 32;
                float acc = 0.f;
#pragma unroll
                for (int c = 0; c < 32; c++) acc += stmp[c * 64 + pos] * w[c];
                dstq[d * 65 + pos] = acc;
            }
            __syncthreads();
        }

        // ---- attention: scores + softmax + weighted V ----
        {
            float* sq = sm + OFF_SQ;
            float* sk = sm + OFF_SK;
            float* sv = sm + OFF_SV;
            float* so = sm + OFF_SO;
            const float* posw = p.position + l * 1024;
#pragma unroll
            for (int r = 0; r < 4; r++) {
                int d = wid + 8 * r;
                const float* qd = sq + d * 65;
                const float* kf = sk + lane * 65;
                float s = 0.f;
#pragma unroll
                for (int e = 0; e < 64; e++) s += qd[e] * kf[e];
                s = s * 0.125f + posw[d * 32 + lane];
                float m = warp_max(s);
                float pe = __expf(s - m);
                float den = warp_sum(pe);
                float pr = pe / den;
                float a0 = 0.f, a1 = 0.f;
#pragma unroll
                for (int f = 0; f < 32; f++) {
                    float pf = __shfl_sync(0xffffffffu, pr, f);
                    a0 += pf * sv[f * 65 + lane];
                    a1 += pf * sv[f * 65 + lane + 32];
                }
                so[d * 65 + lane] = a0;
                so[d * 65 + lane + 32] = a1;
            }
        }
        __syncthreads();

        // ---- c1d: (8 -> 16) over "rows", cols = d*8+p2 (256) ----
        {
            float* so = sm + OFF_SO;
            float* so16 = sm + OFF_SO16;
            int col = tid;
            int d = col >> 3, p2 = col & 7;
            float vals[8];
#pragma unroll
            for (int c = 0; c < 8; c++) vals[c] = so[d * 65 + c * 8 + p2];
            const float* w = p.c1d_w + l * 128;
            const float* bb = p.c1d_b + l * 16;
#pragma unroll
            for (int o = 0; o < 16; o++) {
                float acc = bb[o];
#pragma unroll
                for (int c = 0; c < 8; c++) acc += w[o * 8 + c] * vals[c];
                so16[o * 257 + col] = acc;
            }
        }
        __syncthreads();

        // ---- lin: out[c16][o512] = sum_d so16[c][d] * lin_w[o][d]; x += out ----
        {
            float* wt = sm + OFF_WT;
            float* so16 = sm + OFF_SO16;
            const float* lw = p.lin_w + (size_t)l * 131072;
            float acc[16][2];
#pragma unroll
            for (int c = 0; c < 16; c++) { acc[c][0] = 0.f; acc[c][1] = 0.f; }
            const int oa = tid, ob = tid + 256;
            for (int db = 0; db < 8; db++) {
                int d0 = db * 32;
                // stage 512x32 weight tile (coalesced float4)
#pragma unroll
                for (int it = 0; it < 16; it++) {
                    int e4 = tid + NT * it;          // 0..4095
                    int o = e4 >> 3, dd4 = (e4 & 7) * 4;
                    float4 v = *(const float4*)(lw + o * 256 + d0 + dd4);
                    float* w = wt + o * 33 + dd4;
                    w[0] = v.x; w[1] = v.y; w[2] = v.z; w[3] = v.w;
                }
                __syncthreads();
#pragma unroll 4
                for (int dd = 0; dd < 32; dd++) {
                    int d = d0 + dd;
                    float wa = wt[oa * 33 + dd];
                    float wb = wt[ob * 33 + dd];
#pragma unroll
                    for (int c = 0; c < 16; c++) {
                        float s = so16[c * 257 + d];
                        acc[c][0] += s * wa;
                        acc[c][1] += s * wb;
                    }
                }
                __syncthreads();
            }
            const float* lb = p.lin_b + l * 512;
            float ba = lb[oa], bv = lb[ob];
#pragma unroll
            for (int c = 0; c < 16; c++) {
                sx[c * 512 + oa] += acc[c][0] + ba;
                sx[c * 512 + ob] += acc[c][1] + bv;
            }
        }
        __syncthreads();

        // ================= conv-FFN sublayer =================
        ln_to_patches(sx, sm + OFF_SXP2, p.ln2_g + l * DM, p.ln2_b + l * DM, lane, wid);
        // preload f1 weights
        {
            float* sw1 = sm + OFF_SW1;
            const float* w = p.f1_w + l * 4096;
#pragma unroll
            for (int it = 0; it < 16; it++) sw1[tid + NT * it] = w[tid + NT * it];
        }
        __syncthreads();

        // ---- f1: 32->128 + ReLU, store bf16 t1[c][pos] ----
        {
            __nv_bfloat16* st1 = (__nv_bfloat16*)(sm + OFF_ST1);
            float* sxp2 = sm + OFF_SXP2;
            float* sw1 = sm + OFF_SW1;
            const float* f1b = p.f1_b + l * 128;
            float sv_[32];
#pragma unroll
            for (int i = 0; i < 32; i++) sv_[i] = sxp2[i * 256 + tid];
            for (int c0 = 0; c0 < 128; c0 += 4) {
                float a[4];
#pragma unroll
                for (int j = 0; j < 4; j++) a[j] = f1b[c0 + j];
#pragma unroll
                for (int i = 0; i < 32; i++) {
                    float s = sv_[i];
#pragma unroll
                    for (int j = 0; j < 4; j++) a[j] += s * sw1[(c0 + j) * 32 + i];
                }
#pragma unroll
                for (int j = 0; j < 4; j++)
                    st1[(c0 + j) * 260 + tid] = __float2bfloat16(fmaxf(a[j], 0.f));
            }
        }
        __syncthreads();

        // ---- load fpw / f2 / folded dw weights ----
        {
            float* sfpw = sm + OFF_SFPW;
            const float* w = p.fpw_w + (size_t)l * 16384;
#pragma unroll
            for (int it = 0; it < 64; it++) sfpw[tid + NT * it] = w[tid + NT * it];
            float* sf2 = sm + OFF_SF2;
            const float* w2 = p.f2_w + l * 4096;
#pragma unroll
            for (int it = 0; it < 16; it++) sf2[tid + NT * it] = w2[tid + NT * it];
            float* sfdw = sm + OFF_SFDW;
            if (tid < 128) {
                int c = tid;
                const float* dwp = p.fdw_w + l * 1152 + c * 9;
#pragma unroll
                for (int k = 0; k < 9; k++) sfdw[c * 12 + k] = dwp[k];
                float sc = p.f_bng[l * 128 + c] * rsqrtf(p.f_bnv[l * 128 + c] + EPSLN);
                sfdw[c * 12 + 9] = sc;
                sfdw[c * 12 + 10] = (p.fdw_b[l * 128 + c] - p.f_bnm[l * 128 + c]) * sc
                                    + p.f_bnb[l * 128 + c];
            }
        }
        __syncthreads();

        // ---- fused dw3x3+BN -> fpw+ReLU -> f2 -> residual, 2 rows at a time ----
        {
            __nv_bfloat16* st1 = (__nv_bfloat16*)(sm + OFF_ST1);
            float* sfpw = sm + OFF_SFPW;
            float* st2 = sm + OFF_ST2;
            float* st3 = sm + OFF_ST3;
            float* sf2 = sm + OFF_SF2;
            float* sfdw = sm + OFF_SFDW;
            const float* fpwb = p.fpw_b + l * 128;
            const float* f2b = p.f2_b + l * 32;

            for (int hb = 0; hb < 8; hb++) {
                int h0 = hb * 2;
                // (a) depthwise 3x3 s1 + BN on rows h0,h0+1 -> st2[c][32]
#pragma unroll 4
                for (int it = 0; it < 16; it++) {
                    int u = tid + NT * it;
                    int c = u >> 5, ppos = u & 31;
                    int rr = ppos >> 4, w = ppos & 15;
                    int h = h0 + rr;
                    const float* fw = sfdw + c * 12;
                    float acc = 0.f;
#pragma unroll
                    for (int kh = 0; kh < 3; kh++) {
                        int ih = h - 1 + kh;
                        if ((unsigned)ih < 16u) {
#pragma unroll
                            for (int kw = 0; kw < 3; kw++) {
                                int iw = w - 1 + kw;
                                if ((unsigned)iw < 16u)
                                    acc += __bfloat162float(st1[c * 260 + ih * 16 + iw])
                                           * fw[kh * 3 + kw];
                            }
                        }
                    }
                    st2[c * 34 + ppos] = acc * fw[9] + fw[10];
                }
                __syncthreads();

                // (b) fpw 128->128 + ReLU -> st3
                {
                    int p0 = tid & 15, p1 = p0 + 16;
                    int oblk = tid >> 4;       // 0..15, 8 outputs each
                    float a0[8], a1[8];
#pragma unroll
                    for (int j = 0; j < 8; j++) {
                        float bv = fpwb[oblk * 8 + j];
                        a0[j] = bv; a1[j] = bv;
                    }
#pragma unroll 4
                    for (int c = 0; c < 128; c++) {
                        float s0 = st2[c * 34 + p0];
                        float s1 = st2[c * 34 + p1];
#pragma unroll
                        for (int j = 0; j < 8; j++) {
                            float w = sfpw[(oblk * 8 + j) * 128 + c];
                            a0[j] += s0 * w;
                            a1[j] += s1 * w;
                        }
                    }
#pragma unroll
                    for (int j = 0; j < 8; j++) {
                        int o = oblk * 8 + j;
                        st3[o * 33 + p0] = fmaxf(a0[j], 0.f);
                        st3[o * 33 + p1] = fmaxf(a1[j], 0.f);
                    }
                }
                __syncthreads();

                // (c) f2 128->32 + residual into sx
                {
                    int pp = tid & 31;
                    int iblk = tid >> 5;       // 0..7, 4 outputs each
                    float acc[4];
#pragma unroll
                    for (int j = 0; j < 4; j++) acc[j] = f2b[iblk * 4 + j];
#pragma unroll 4
                    for (int o = 0; o < 128; o++) {
                        float s = st3[o * 33 + pp];
#pragma unroll
                        for (int j = 0; j < 4; j++)
                            acc[j] += sf2[(iblk * 4 + j) * 128 + o] * s;
                    }
                    int h = h0 + (pp >> 4), w = pp & 15;
#pragma unroll
                    for (int j = 0; j < 4; j++) {
                        int i = iblk * 4 + j;
                        sx[h * 512 + i * 16 + w] += acc[j];
                    }
                }
                __syncthreads();
            }
        }
    } // layers

    __syncthreads();
    // ---- write out ----
    {
        float4* og = (float4*)(p.out + (size_t)b * 8192);
        const float4* sx4 = (const float4*)sx;
#pragma unroll
        for (int it = 0; it < 8; it++) og[tid + NT * it] = sx4[tid + NT * it];
    }
}

extern "C" void kernel_launch(void* const* d_in, const int* in_sizes, int n_in,
                              void* d_out, int out_size) {
    Params p;
    p.x        = (const float*)d_in[0];
    p.ln1_g    = (const float*)d_in[1];
    p.ln1_b    = (const float*)d_in[2];
    p.ln2_g    = (const float*)d_in[3];
    p.ln2_b    = (const float*)d_in[4];
    p.qkv_dw   = (const float*)d_in[5];
    p.qkv_bng  = (const float*)d_in[6];
    p.qkv_bnb  = (const float*)d_in[7];
    p.qkv_bnm  = (const float*)d_in[8];
    p.qkv_bnv  = (const float*)d_in[9];
    p.qkv_pw   = (const float*)d_in[10];
    p.position = (const float*)d_in[11];
    p.c1d_w    = (const float*)d_in[12];
    p.c1d_b    = (const float*)d_in[13];
    p.lin_w    = (const float*)d_in[14];
    p.lin_b    = (const float*)d_in[15];
    p.f1_w     = (const float*)d_in[16];
    p.f1_b     = (const float*)d_in[17];
    p.fdw_w    = (const float*)d_in[18];
    p.fdw_b    = (const float*)d_in[19];
    p.f_bng    = (const float*)d_in[20];
    p.f_bnb    = (const float*)d_in[21];
    p.f_bnm    = (const float*)d_in[22];
    p.f_bnv    = (const float*)d_in[23];
    p.fpw_w    = (const float*)d_in[24];
    p.fpw_b    = (const float*)d_in[25];
    p.f2_w     = (const float*)d_in[26];
    p.f2_b     = (const float*)d_in[27];
    p.out      = (float*)d_out;

    int nb = in_sizes[0] / (16 * 512);   // = 2048

    // idempotent every call; legal during graph capture (not a stream op)
    cudaFuncSetAttribute(encoder_kernel,
                         cudaFuncAttributeMaxDynamicSharedMemorySize, SMEM_BYTES);

    encoder_kernel<<<nb, NT, SMEM_BYTES>>>(p);
}